// round 11
// baseline (speedup 1.0000x reference)
#include <cuda_runtime.h>
#include <math.h>

// Skipgram negative-sampling loss — fused kernel at the LTS roofline.
// Gather path = measured-best variant (10 neg rows via cp.async.cg, one
// commit group; center/pos via LDG). Completion tail is a 3-level
// hierarchical reduction (block -> bucket-of-32 -> global) so almost all
// reduction work overlaps the gather of still-running blocks; only the
// 64-way final sum is exposed.
// Inputs (metadata order):
//   d_in[0] center_id       int32 [B]
//   d_in[1] pos_context_id  int32 [B]
//   d_in[2] neg_context_ids int32 [B, K]
//   d_in[3] W_in            f32   [VOCAB, DIM]
//   d_in[4] W_out           f32   [VOCAB, DIM]
// Output: scalar f32 = -(sum log_sigmoid(pos_score) + sum log_sigmoid(-neg_score))

#define BATCH   16384
#define KNEG    10
#define DIMV4   32          // 128 floats = 32 float4 per row
#define WPB     8           // warps per block
#define NBLK    2048        // BATCH / WPB
#define NBUCKET 64
#define BPB     32          // blocks per bucket (contiguous blockIdx)

struct PaddedCtr { unsigned int v; unsigned int pad[31]; };   // 128B stride

__device__ float g_partial[NBLK];
__device__ float g_bucket[NBUCKET];
__device__ PaddedCtr g_cnt1[NBUCKET];   // zero-init; reset by final block
__device__ unsigned int g_cnt2 = 0;

__device__ __forceinline__ float log_sigmoid(float x) {
    return fminf(x, 0.0f) - log1pf(__expf(-fabsf(x)));
}

__device__ __forceinline__ void cp_async16(void* smem_dst, const void* gmem_src) {
    unsigned int s = (unsigned int)__cvta_generic_to_shared(smem_dst);
    asm volatile("cp.async.cg.shared.global [%0], [%1], 16;\n" :: "r"(s), "l"(gmem_src));
}

__global__ __launch_bounds__(256) void skipgram_fused(
    const int* __restrict__ center_id,
    const int* __restrict__ pos_id,
    const int* __restrict__ neg_ids,
    const float4* __restrict__ Win,
    const float4* __restrict__ Wout,
    float* __restrict__ out)
{
    // Staging buffer: 10 neg rows per warp, lane-sliced. 8*10*32*16B = 40KB.
    __shared__ float4 buf[WPB][KNEG][32];
    __shared__ float s[WPB];

    const int lane = threadIdx.x & 31;
    const int w    = threadIdx.x >> 5;
    const int b    = blockIdx.x * WPB + w;   // one warp per batch element

    // ---- Indices ----
    const int cid = center_id[b];
    const int pid = pos_id[b];
    int my_nid = 0;
    if (lane < KNEG) my_nid = neg_ids[b * KNEG + lane];

    // ---- Direct loads for center/pos ----
    const float4 c = Win [(unsigned)cid * DIMV4 + (unsigned)lane];
    const float4 p = Wout[(unsigned)pid * DIMV4 + (unsigned)lane];

    // ---- Async gather of all 10 negative rows ----
#pragma unroll
    for (int k = 0; k < KNEG; ++k) {
        const unsigned id = (unsigned)__shfl_sync(0xffffffffu, my_nid, k);
        cp_async16(&buf[w][k][lane], Wout + (id * DIMV4 + (unsigned)lane));
    }
    asm volatile("cp.async.commit_group;\n" ::: "memory");
    asm volatile("cp.async.wait_group 0;\n" ::: "memory");
    __syncwarp();

    // ---- Reduce: two accumulator chains over smem rows ----
    float4 na = make_float4(0.f, 0.f, 0.f, 0.f);
    float4 nb = make_float4(0.f, 0.f, 0.f, 0.f);
#pragma unroll
    for (int k = 0; k < KNEG; k += 2) {
        const float4 va = buf[w][k][lane];
        const float4 vb = buf[w][k + 1][lane];
        na.x += va.x; na.y += va.y; na.z += va.z; na.w += va.w;
        nb.x += vb.x; nb.y += vb.y; nb.z += vb.z; nb.w += vb.w;
    }
    const float4 nsum = make_float4(na.x + nb.x, na.y + nb.y, na.z + nb.z, na.w + nb.w);

    float pd = c.x * p.x + c.y * p.y + c.z * p.z + c.w * p.w;
    float nd = c.x * nsum.x + c.y * nsum.y + c.z * nsum.z + c.w * nsum.w;

#pragma unroll
    for (int o = 16; o > 0; o >>= 1) {
        pd += __shfl_xor_sync(0xffffffffu, pd, o);
        nd += __shfl_xor_sync(0xffffffffu, nd, o);
    }

    if (lane == 0)
        s[w] = log_sigmoid(pd) + log_sigmoid(-nd);
    __syncthreads();

    // ---- Hierarchical completion (warp 0 only; other warps exit) ----
    if (w != 0) return;

    // Level 0: block sum (lanes 0..7 hold warp sums).
    float t = (lane < WPB) ? s[lane] : 0.f;
#pragma unroll
    for (int o = 4; o > 0; o >>= 1)
        t += __shfl_xor_sync(0xffffffffu, t, o);

    const unsigned bucket = blockIdx.x >> 5;   // 32 contiguous blocks per bucket
    int last1 = 0;
    if (lane == 0) {
        g_partial[blockIdx.x] = t;
        __threadfence();                                    // release partial
        last1 = (atomicAdd(&g_cnt1[bucket].v, 1u) == BPB - 1);
    }
    last1 = __shfl_sync(0xffffffffu, last1, 0);
    if (!last1) return;

    // Level 1: bucket-last block reduces its 32 contiguous partials.
    // This overlaps with other buckets' blocks still gathering.
    __threadfence();                                        // acquire partials
    float u = g_partial[bucket * BPB + lane];               // 32 lanes, 128B
#pragma unroll
    for (int o = 16; o > 0; o >>= 1)
        u += __shfl_xor_sync(0xffffffffu, u, o);

    int last2 = 0;
    if (lane == 0) {
        g_bucket[bucket] = u;
        __threadfence();                                    // release bucket sum
        last2 = (atomicAdd(&g_cnt2, 1u) == NBUCKET - 1);
    }
    last2 = __shfl_sync(0xffffffffu, last2, 0);
    if (!last2) return;

    // Level 2: global-last block reduces the 64 bucket sums (exposed tail).
    __threadfence();                                        // acquire bucket sums
    float v = g_bucket[lane] + g_bucket[lane + 32];         // fixed order
#pragma unroll
    for (int o = 16; o > 0; o >>= 1)
        v += __shfl_xor_sync(0xffffffffu, v, o);

    // Reset counters for next graph replay (each lane two buckets).
    g_cnt1[lane].v = 0;
    g_cnt1[lane + 32].v = 0;
    if (lane == 0) {
        out[0] = -v;
        g_cnt2 = 0;
    }
}

extern "C" void kernel_launch(void* const* d_in, const int* in_sizes, int n_in,
                              void* d_out, int out_size)
{
    const int*    center_id = (const int*)   d_in[0];
    const int*    pos_id    = (const int*)   d_in[1];
    const int*    neg_ids   = (const int*)   d_in[2];
    const float4* Win       = (const float4*)d_in[3];
    const float4* Wout      = (const float4*)d_in[4];
    float* out = (float*)d_out;

    skipgram_fused<<<NBLK, 256>>>(center_id, pos_id, neg_ids, Win, Wout, out);
}

// round 12
// speedup vs baseline: 1.4531x; 1.4531x over previous
#include <cuda_runtime.h>
#include <math.h>

// Skipgram negative-sampling loss — fused kernel at the LTS roofline.
// Gather path: 10 neg rows per batch element via cp.async.cg (one commit
// group, lane-sliced 512B rows), center/pos via LDG.128. One warp per
// batch element. Single-counter last-block completion, warp-parallel
// vectorized final reduction. Measured 14.85us = ~98% of the GB300 L2
// sector-service cap for the irreducible 100.7MB gather.
// Inputs (metadata order):
//   d_in[0] center_id       int32 [B]
//   d_in[1] pos_context_id  int32 [B]
//   d_in[2] neg_context_ids int32 [B, K]
//   d_in[3] W_in            f32   [VOCAB, DIM]
//   d_in[4] W_out           f32   [VOCAB, DIM]
// Output: scalar f32 = -(sum log_sigmoid(pos_score) + sum log_sigmoid(-neg_score))

#define BATCH 16384
#define KNEG  10
#define DIMV4 32          // 128 floats = 32 float4 per row
#define WPB   8           // warps per block
#define NBLK  2048        // BATCH / WPB

__device__ float4 g_partial4[NBLK / 4];   // partials, float4-addressable
__device__ unsigned int g_count = 0;      // reset by last block each call

__device__ __forceinline__ float log_sigmoid(float x) {
    return fminf(x, 0.0f) - log1pf(__expf(-fabsf(x)));
}

__device__ __forceinline__ void cp_async16(void* smem_dst, const void* gmem_src) {
    unsigned int s = (unsigned int)__cvta_generic_to_shared(smem_dst);
    asm volatile("cp.async.cg.shared.global [%0], [%1], 16;\n" :: "r"(s), "l"(gmem_src));
}

__global__ __launch_bounds__(256) void skipgram_fused(
    const int* __restrict__ center_id,
    const int* __restrict__ pos_id,
    const int* __restrict__ neg_ids,
    const float4* __restrict__ Win,
    const float4* __restrict__ Wout,
    float* __restrict__ out)
{
    // Staging buffer: 10 neg rows per warp, lane-sliced. 8*10*32*16B = 40KB.
    __shared__ float4 buf[WPB][KNEG][32];
    __shared__ float s[WPB];
    __shared__ bool is_last;

    const int lane = threadIdx.x & 31;
    const int w    = threadIdx.x >> 5;
    const int b    = blockIdx.x * WPB + w;   // one warp per batch element

    // ---- Indices ----
    const int cid = center_id[b];
    const int pid = pos_id[b];
    int my_nid = 0;
    if (lane < KNEG) my_nid = neg_ids[b * KNEG + lane];

    // ---- Direct loads for center/pos ----
    const float4 c = Win [(unsigned)cid * DIMV4 + (unsigned)lane];
    const float4 p = Wout[(unsigned)pid * DIMV4 + (unsigned)lane];

    // ---- Async gather of all 10 negative rows ----
#pragma unroll
    for (int k = 0; k < KNEG; ++k) {
        const unsigned id = (unsigned)__shfl_sync(0xffffffffu, my_nid, k);
        cp_async16(&buf[w][k][lane], Wout + (id * DIMV4 + (unsigned)lane));
    }
    asm volatile("cp.async.commit_group;\n" ::: "memory");
    asm volatile("cp.async.wait_group 0;\n" ::: "memory");
    __syncwarp();

    // ---- Reduce: two accumulator chains over smem rows ----
    float4 na = make_float4(0.f, 0.f, 0.f, 0.f);
    float4 nb = make_float4(0.f, 0.f, 0.f, 0.f);
#pragma unroll
    for (int k = 0; k < KNEG; k += 2) {
        const float4 va = buf[w][k][lane];
        const float4 vb = buf[w][k + 1][lane];
        na.x += va.x; na.y += va.y; na.z += va.z; na.w += va.w;
        nb.x += vb.x; nb.y += vb.y; nb.z += vb.z; nb.w += vb.w;
    }
    const float4 nsum = make_float4(na.x + nb.x, na.y + nb.y, na.z + nb.z, na.w + nb.w);

    float pd = c.x * p.x + c.y * p.y + c.z * p.z + c.w * p.w;
    float nd = c.x * nsum.x + c.y * nsum.y + c.z * nsum.z + c.w * nsum.w;

#pragma unroll
    for (int o = 16; o > 0; o >>= 1) {
        pd += __shfl_xor_sync(0xffffffffu, pd, o);
        nd += __shfl_xor_sync(0xffffffffu, nd, o);
    }

    if (lane == 0)
        s[w] = log_sigmoid(pd) + log_sigmoid(-nd);
    __syncthreads();

    // ---- Per-block epilogue: warp 0 sums the 8 warp results in parallel ----
    if (w == 0) {
        float t = (lane < WPB) ? s[lane] : 0.f;
#pragma unroll
        for (int o = 4; o > 0; o >>= 1)
            t += __shfl_xor_sync(0xffffffffu, t, o);

        if (lane == 0) {
            ((float*)g_partial4)[blockIdx.x] = t;
            __threadfence();
            unsigned int old = atomicAdd(&g_count, 1u);
            is_last = (old == NBLK - 1);
        }
    }
    __syncthreads();

    if (is_last) {
        // Deterministic fixed-order reduction: 512 float4 over 256 threads.
        float4 a = g_partial4[threadIdx.x];
        float4 d = g_partial4[threadIdx.x + 256];
        float t = (a.x + a.y) + (a.z + a.w) + (d.x + d.y) + (d.z + d.w);

#pragma unroll
        for (int o = 16; o > 0; o >>= 1)
            t += __shfl_xor_sync(0xffffffffu, t, o);

        __shared__ float s2[WPB];
        if (lane == 0) s2[w] = t;
        __syncthreads();

        if (w == 0) {
            float tot = (lane < WPB) ? s2[lane] : 0.f;
#pragma unroll
            for (int o = 4; o > 0; o >>= 1)
                tot += __shfl_xor_sync(0xffffffffu, tot, o);
            if (lane == 0) {
                out[0] = -tot;
                g_count = 0;   // reset for next graph replay
            }
        }
    }
}

extern "C" void kernel_launch(void* const* d_in, const int* in_sizes, int n_in,
                              void* d_out, int out_size)
{
    const int*    center_id = (const int*)   d_in[0];
    const int*    pos_id    = (const int*)   d_in[1];
    const int*    neg_ids   = (const int*)   d_in[2];
    const float4* Win       = (const float4*)d_in[3];
    const float4* Wout      = (const float4*)d_in[4];
    float* out = (float*)d_out;

    skipgram_fused<<<NBLK, 256>>>(center_id, pos_id, neg_ids, Win, Wout, out);
}

// round 14
// speedup vs baseline: 1.5690x; 1.0797x over previous
#include <cuda_runtime.h>
#include <math.h>

// Skipgram negative-sampling loss — single-wave persistent fused kernel.
// 683 blocks x 256 threads (= one wave at 5 blocks/SM with 40KB smem);
// each warp sequentially processes 3 batch elements, staging the 10 negative
// rows of each element via cp.async.cg into its warp-private smem slice.
// Sustained (not bursty) ~400 in-flight rows/SM; no CTA churn, no wave
// transitions. Single-counter last-block completion.
// Inputs (metadata order):
//   d_in[0] center_id       int32 [B]
//   d_in[1] pos_context_id  int32 [B]
//   d_in[2] neg_context_ids int32 [B, K]
//   d_in[3] W_in            f32   [VOCAB, DIM]
//   d_in[4] W_out           f32   [VOCAB, DIM]
// Output: scalar f32 = -(sum log_sigmoid(pos_score) + sum log_sigmoid(-neg_score))

#define BATCH 16384
#define KNEG  10
#define DIMV4 32          // 128 floats = 32 float4 per row
#define WPB   8           // warps per block
#define EPW   3           // batch elements per warp (sequential)
#define NBLKP 683         // ceil(16384 / (8*3)); 683*24 = 16392 (8 masked)
#define NPAD  768         // padded partial count (3*256)

__device__ float g_partial[NPAD];        // slots >= NBLKP stay 0 forever
__device__ unsigned int g_count = 0;     // reset by last block each call

__device__ __forceinline__ float log_sigmoid(float x) {
    return fminf(x, 0.0f) - log1pf(__expf(-fabsf(x)));
}

__device__ __forceinline__ void cp_async16(void* smem_dst, const void* gmem_src) {
    unsigned int s = (unsigned int)__cvta_generic_to_shared(smem_dst);
    asm volatile("cp.async.cg.shared.global [%0], [%1], 16;\n" :: "r"(s), "l"(gmem_src));
}

__global__ __launch_bounds__(256) void skipgram_fused(
    const int* __restrict__ center_id,
    const int* __restrict__ pos_id,
    const int* __restrict__ neg_ids,
    const float4* __restrict__ Win,
    const float4* __restrict__ Wout,
    float* __restrict__ out)
{
    // Staging: 10 neg rows per warp, lane-sliced. 8*10*32*16B = 40KB.
    __shared__ float4 buf[WPB][KNEG][32];
    __shared__ float s[WPB];
    __shared__ bool is_last;

    const int lane = threadIdx.x & 31;
    const int w    = threadIdx.x >> 5;
    const int g    = blockIdx.x * WPB + w;   // global warp id

    float loss = 0.f;   // identical value on all lanes

#pragma unroll
    for (int i = 0; i < EPW; ++i) {
        const int b = g * EPW + i;
        if (b < BATCH) {
            // ---- Indices ----
            const int cid = center_id[b];
            const int pid = pos_id[b];
            int my_nid = 0;
            if (lane < KNEG) my_nid = neg_ids[b * KNEG + lane];

            // ---- Async gather of all 10 negative rows ----
            // In-order issue guarantees the previous iteration's smem reads
            // were consumed (their FADD consumers issued) before these writes.
#pragma unroll
            for (int k = 0; k < KNEG; ++k) {
                const unsigned id = (unsigned)__shfl_sync(0xffffffffu, my_nid, k);
                cp_async16(&buf[w][k][lane], Wout + (id * DIMV4 + (unsigned)lane));
            }
            asm volatile("cp.async.commit_group;\n" ::: "memory");

            // ---- Direct loads overlap with the async gather ----
            const float4 c = Win [(unsigned)cid * DIMV4 + (unsigned)lane];
            const float4 p = Wout[(unsigned)pid * DIMV4 + (unsigned)lane];

            asm volatile("cp.async.wait_group 0;\n" ::: "memory");
            __syncwarp();

            // ---- Reduce: two accumulator chains over smem rows ----
            float4 na = make_float4(0.f, 0.f, 0.f, 0.f);
            float4 nb = make_float4(0.f, 0.f, 0.f, 0.f);
#pragma unroll
            for (int k = 0; k < KNEG; k += 2) {
                const float4 va = buf[w][k][lane];
                const float4 vb = buf[w][k + 1][lane];
                na.x += va.x; na.y += va.y; na.z += va.z; na.w += va.w;
                nb.x += vb.x; nb.y += vb.y; nb.z += vb.z; nb.w += vb.w;
            }
            const float4 ns = make_float4(na.x + nb.x, na.y + nb.y,
                                          na.z + nb.z, na.w + nb.w);

            float pd = c.x * p.x + c.y * p.y + c.z * p.z + c.w * p.w;
            float nd = c.x * ns.x + c.y * ns.y + c.z * ns.z + c.w * ns.w;

#pragma unroll
            for (int o = 16; o > 0; o >>= 1) {
                pd += __shfl_xor_sync(0xffffffffu, pd, o);
                nd += __shfl_xor_sync(0xffffffffu, nd, o);
            }

            loss += log_sigmoid(pd) + log_sigmoid(-nd);
        }
    }

    if (lane == 0)
        s[w] = loss;
    __syncthreads();

    // ---- Per-block epilogue: warp 0 sums the 8 warp results ----
    if (w == 0) {
        float t = (lane < WPB) ? s[lane] : 0.f;
#pragma unroll
        for (int o = 4; o > 0; o >>= 1)
            t += __shfl_xor_sync(0xffffffffu, t, o);

        if (lane == 0) {
            g_partial[blockIdx.x] = t;
            __threadfence();
            unsigned int old = atomicAdd(&g_count, 1u);
            is_last = (old == NBLKP - 1);
        }
    }
    __syncthreads();

    if (is_last) {
        // Deterministic fixed-order reduction: 768 slots over 256 threads
        // (slots >= 683 are never written and remain 0).
        float t = g_partial[threadIdx.x]
                + g_partial[threadIdx.x + 256]
                + g_partial[threadIdx.x + 512];

#pragma unroll
        for (int o = 16; o > 0; o >>= 1)
            t += __shfl_xor_sync(0xffffffffu, t, o);

        __shared__ float s2[WPB];
        if (lane == 0) s2[w] = t;
        __syncthreads();

        if (w == 0) {
            float tot = (lane < WPB) ? s2[lane] : 0.f;
#pragma unroll
            for (int o = 4; o > 0; o >>= 1)
                tot += __shfl_xor_sync(0xffffffffu, tot, o);
            if (lane == 0) {
                out[0] = -tot;
                g_count = 0;   // reset for next graph replay
            }
        }
    }
}

extern "C" void kernel_launch(void* const* d_in, const int* in_sizes, int n_in,
                              void* d_out, int out_size)
{
    const int*    center_id = (const int*)   d_in[0];
    const int*    pos_id    = (const int*)   d_in[1];
    const int*    neg_ids   = (const int*)   d_in[2];
    const float4* Win       = (const float4*)d_in[3];
    const float4* Wout      = (const float4*)d_in[4];
    float* out = (float*)d_out;

    skipgram_fused<<<NBLKP, 256>>>(center_id, pos_id, neg_ids, Win, Wout, out);
}